// round 1
// baseline (speedup 1.0000x reference)
#include <cuda_runtime.h>
#include <cuda_bf16.h>
#include <math.h>

#define NN   4096
#define EE   131072
#define TT   8
#define RR   16
#define HH   8
#define BB   21

// ---------------------------------------------------------------------------
// Fill kernel: out[h, i, j] = typepair[tt[i], tt[j], h]  (+ temporal for seeds)
// blockIdx.y = row i; each thread covers 4 consecutive j as float4, all 8 h.
// ---------------------------------------------------------------------------
__global__ void __launch_bounds__(256)
fill_kernel(const int*   __restrict__ token_type,
            const float* __restrict__ time_vec,
            const float* __restrict__ typepair_bias,  // [T,T,H] = 512
            const float* __restrict__ temp_bias,      // [B,H]   = 168
            const int*   __restrict__ seed_ptr,       // may be null
            float*       __restrict__ out)
{
    __shared__ float s_tp[TT * TT * HH];  // 512 floats
    __shared__ float s_tb[BB * HH];       // 168 floats

    const int tid = threadIdx.x;
    for (int k = tid; k < TT * TT * HH; k += blockDim.x) s_tp[k] = typepair_bias[k];
    for (int k = tid; k < BB * HH;      k += blockDim.x) s_tb[k] = temp_bias[k];
    __syncthreads();

    const int i  = blockIdx.y;
    const int j0 = (blockIdx.x * blockDim.x + tid) * 4;

    const int tti = token_type[i];                                   // uniform per block
    const int4 ttj = *reinterpret_cast<const int4*>(token_type + j0);

    const int seed = seed_ptr ? *seed_ptr : 128;
    const bool is_seed = (i < seed);

    int bkt0 = 0, bkt1 = 0, bkt2 = 0, bkt3 = 0;
    if (is_seed) {
        const float tvi  = time_vec[i];
        const float4 tvj = *reinterpret_cast<const float4*>(time_vec + j0);
        float dts[4] = { tvj.x - tvi, tvj.y - tvi, tvj.z - tvi, tvj.w - tvi };
        int bk[4];
        #pragma unroll
        for (int q = 0; q < 4; q++) {
            float dt = dts[q];
            float sg = (dt > 0.f) ? 1.f : ((dt < 0.f) ? -1.f : 0.f);
            float sl = sg * log1pf(fabsf(dt) + 1e-6f);
            // (clip(sl,-5,5) - (-5)) / (10 + 1e-9); 10+1e-9 == 10 in f32
            float nrm = (fminf(fmaxf(sl, -5.f), 5.f) + 5.f) * (1.0f / 10.0f);
            int idx = (int)floorf(nrm * (float)(BB - 1));
            bk[q] = min(max(idx, 0), BB - 1);
        }
        bkt0 = bk[0]; bkt1 = bk[1]; bkt2 = bk[2]; bkt3 = bk[3];
    }

    const float* tp = s_tp + tti * (TT * HH);
    const int o0 = ttj.x * HH, o1 = ttj.y * HH, o2 = ttj.z * HH, o3 = ttj.w * HH;
    const size_t rowbase = (size_t)i * NN + (size_t)j0;

    #pragma unroll
    for (int h = 0; h < HH; h++) {
        float4 v;
        v.x = tp[o0 + h];
        v.y = tp[o1 + h];
        v.z = tp[o2 + h];
        v.w = tp[o3 + h];
        if (is_seed) {
            v.x += s_tb[bkt0 * HH + h];
            v.y += s_tb[bkt1 * HH + h];
            v.z += s_tb[bkt2 * HH + h];
            v.w += s_tb[bkt3 * HH + h];
        }
        float4* dst = reinterpret_cast<float4*>(out + (size_t)h * NN * NN + rowbase);
        __stcs(dst, v);   // streaming store: output >> L2 capacity
    }
}

// ---------------------------------------------------------------------------
// Edge scatter: out[h, src, dst] += adj_rel_bias[rel, h]
// Duplicate (src,dst) pairs exist -> atomics required.
// ---------------------------------------------------------------------------
__global__ void __launch_bounds__(256)
edge_kernel(const int*   __restrict__ edge_src,
            const int*   __restrict__ edge_dst,
            const int*   __restrict__ edge_rel,
            const float* __restrict__ adj_rel_bias,   // [R,H] = 128
            float*       __restrict__ out,
            int n_edges)
{
    int e = blockIdx.x * blockDim.x + threadIdx.x;
    if (e >= n_edges) return;
    const int s = edge_src[e];
    const int d = edge_dst[e];
    const int r = edge_rel[e];
    const size_t base = (size_t)s * NN + (size_t)d;
    #pragma unroll
    for (int h = 0; h < HH; h++) {
        atomicAdd(out + (size_t)h * NN * NN + base, __ldg(adj_rel_bias + r * HH + h));
    }
}

// ---------------------------------------------------------------------------
extern "C" void kernel_launch(void* const* d_in, const int* in_sizes, int n_in,
                              void* d_out, int out_size)
{
    const int*   token_type = (const int*)  d_in[0];
    const int*   edge_src   = (const int*)  d_in[1];
    const int*   edge_dst   = (const int*)  d_in[2];
    const int*   edge_rel   = (const int*)  d_in[3];
    const float* time_vec   = (const float*)d_in[4];

    // seed_count may appear as a 1-element int tensor at slot 5, or be absent.
    const int*   seed_ptr = nullptr;
    int bias_base = 5;
    if (n_in >= 9 && in_sizes[5] == 1) {
        seed_ptr  = (const int*)d_in[5];
        bias_base = 6;
    }
    const float* adj_rel_bias  = (const float*)d_in[bias_base + 0];  // [R,H]
    const float* typepair_bias = (const float*)d_in[bias_base + 1];  // [T,T,H]
    const float* temp_bias     = (const float*)d_in[bias_base + 2];  // [B,H]

    float* out = (float*)d_out;

    const int n_edges = in_sizes[1];

    // Fill: one block-row per i, 4 blocks across j (256 thr * 4 j each = 1024 j/blk)
    dim3 fgrid(NN / (256 * 4), NN);
    fill_kernel<<<fgrid, 256>>>(token_type, time_vec, typepair_bias, temp_bias,
                                seed_ptr, out);

    // Edge scatter
    int eblocks = (n_edges + 255) / 256;
    edge_kernel<<<eblocks, 256>>>(edge_src, edge_dst, edge_rel, adj_rel_bias,
                                  out, n_edges);
}

// round 8
// speedup vs baseline: 1.0186x; 1.0186x over previous
#include <cuda_runtime.h>
#include <cuda_bf16.h>
#include <math.h>

#define NN   4096
#define TT   8
#define RR   16
#define HH   8
#define BB   21
#define CAP  128   // max edges bucketed per src row (avg 32, Poisson; 128 is ~17 sigma)
#define THR  256   // threads per fill block
#define JPB  (THR * 4)  // j columns covered per block (1024)

// __device__ scratch (no allocation allowed in kernel_launch)
__device__ int          g_cnt[NN];
__device__ unsigned int g_buck[NN * CAP];   // packed (rel<<12)|dst

// ---------------------------------------------------------------------------
__global__ void reset_kernel()
{
    int i = blockIdx.x * blockDim.x + threadIdx.x;
    if (i < NN) g_cnt[i] = 0;
}

// Bucket edges by src row. Order within a row is nondeterministic, but the
// fill kernel sums all entries, so the result is order-insensitive (to fp
// rounding, well inside the 1e-3 tolerance).
__global__ void __launch_bounds__(256)
bucket_kernel(const int* __restrict__ edge_src,
              const int* __restrict__ edge_dst,
              const int* __restrict__ edge_rel,
              int n_edges)
{
    int e = blockIdx.x * blockDim.x + threadIdx.x;
    if (e >= n_edges) return;
    const int s = edge_src[e];
    const int d = edge_dst[e];
    const int r = edge_rel[e];
    int pos = atomicAdd(&g_cnt[s], 1);
    if (pos < CAP)
        g_buck[s * CAP + pos] = ((unsigned)r << 12) | (unsigned)d;
}

// 8 FADDs, constant smem offsets — inlined into each switch arm.
__device__ __forceinline__ void add_row(float* __restrict__ v,
                                        const float* __restrict__ ab)
{
#pragma unroll
    for (int h = 0; h < HH; h++) v[h] += ab[h];
}

// ---------------------------------------------------------------------------
// Fused fill: out[h,i,j] = typepair[tt[i],tt[j],h] (+ temporal for seed rows)
//                          (+ adj_rel_bias[rel,h] for edges (i -> j))
// blockIdx.y = row i; each thread covers 4 consecutive j, all 8 h planes.
// All accumulation happens in registers; stores are streaming float4.
// ---------------------------------------------------------------------------
__global__ void __launch_bounds__(THR)
fill_kernel(const int*   __restrict__ token_type,
            const float* __restrict__ time_vec,
            const float* __restrict__ typepair_bias,  // [T,T,H] = 512
            const float* __restrict__ temp_bias,      // [B,H]   = 168
            const float* __restrict__ adj_rel_bias,   // [R,H]   = 128
            const int*   __restrict__ seed_ptr,       // may be null
            float*       __restrict__ out)
{
    __shared__ float        s_tp[TT * TT * HH];  // 512
    __shared__ float        s_tb[BB * HH];       // 168
    __shared__ float        s_adj[RR * HH];      // 128
    __shared__ unsigned int s_edges[CAP];
    __shared__ int          s_ecnt;

    const int tid    = threadIdx.x;
    const int i      = blockIdx.y;
    const int blk_j0 = blockIdx.x * JPB;          // this block's j window start

    for (int k = tid; k < TT * TT * HH; k += THR) s_tp[k]  = typepair_bias[k];
    for (int k = tid; k < BB * HH;      k += THR) s_tb[k]  = temp_bias[k];
    for (int k = tid; k < RR * HH;      k += THR) s_adj[k] = adj_rel_bias[k];
    if (tid == 0) s_ecnt = 0;
    __syncthreads();

    // Compacting load: keep only edges whose dst falls in this block's window.
    {
        int c = g_cnt[i];
        c = (c < CAP) ? c : CAP;
        if (tid < c) {
            unsigned p = g_buck[i * CAP + tid];
            unsigned d = p & 0xFFFu;
            if (d - (unsigned)blk_j0 < (unsigned)JPB) {
                int pos = atomicAdd(&s_ecnt, 1);
                s_edges[pos] = p;
            }
        }
    }
    __syncthreads();
    const int ecnt = s_ecnt;

    const int j0 = blk_j0 + tid * 4;

    const int tti = token_type[i];                                   // uniform per block
    const int4 ttj = *reinterpret_cast<const int4*>(token_type + j0);

    const int seed = seed_ptr ? *seed_ptr : 128;
    const bool is_seed = (i < seed);

    const float* tp = s_tp + tti * (TT * HH);
    const float* t0 = tp + ttj.x * HH;
    const float* t1 = tp + ttj.y * HH;
    const float* t2 = tp + ttj.z * HH;
    const float* t3 = tp + ttj.w * HH;

    // Register tile: 4 j-lanes x 8 heads (named arrays -> constant indexing)
    float va[HH], vb[HH], vc[HH], vd[HH];
#pragma unroll
    for (int h = 0; h < HH; h++) {
        va[h] = t0[h];
        vb[h] = t1[h];
        vc[h] = t2[h];
        vd[h] = t3[h];
    }

    if (is_seed) {
        const float tvi  = time_vec[i];
        const float4 tvj = *reinterpret_cast<const float4*>(time_vec + j0);
        const float dts[4] = { tvj.x - tvi, tvj.y - tvi, tvj.z - tvi, tvj.w - tvi };
        int bk[4];
#pragma unroll
        for (int q = 0; q < 4; q++) {
            float dt = dts[q];
            float sg = (dt > 0.f) ? 1.f : ((dt < 0.f) ? -1.f : 0.f);
            float sl = sg * log1pf(fabsf(dt) + 1e-6f);
            float nrm = (fminf(fmaxf(sl, -5.f), 5.f) + 5.f) * (1.0f / 10.0f);
            int idx = (int)floorf(nrm * (float)(BB - 1));
            bk[q] = min(max(idx, 0), BB - 1);
        }
        add_row(va, s_tb + bk[0] * HH);
        add_row(vb, s_tb + bk[1] * HH);
        add_row(vc, s_tb + bk[2] * HH);
        add_row(vd, s_tb + bk[3] * HH);
    }

    // Edge scan (block-local, ~8 entries): accumulate adj bias for this thread's j.
    for (int e = 0; e < ecnt; e++) {
        const unsigned p = s_edges[e];            // smem broadcast
        const unsigned d = p & 0xFFFu;
        const unsigned delta = d - (unsigned)j0;  // wraps if d < j0
        if (delta < 4u) {
            const float* ab = s_adj + (p >> 12) * HH;
            switch (delta) {
                case 0u: add_row(va, ab); break;
                case 1u: add_row(vb, ab); break;
                case 2u: add_row(vc, ab); break;
                default: add_row(vd, ab); break;
            }
        }
    }

    const size_t rowbase = (size_t)i * NN + (size_t)j0;
#pragma unroll
    for (int h = 0; h < HH; h++) {
        float4 v = make_float4(va[h], vb[h], vc[h], vd[h]);
        float4* dst = reinterpret_cast<float4*>(out + (size_t)h * NN * NN + rowbase);
        __stcs(dst, v);   // streaming store: output >> L2 capacity
    }
}

// ---------------------------------------------------------------------------
extern "C" void kernel_launch(void* const* d_in, const int* in_sizes, int n_in,
                              void* d_out, int out_size)
{
    const int*   token_type = (const int*)  d_in[0];
    const int*   edge_src   = (const int*)  d_in[1];
    const int*   edge_dst   = (const int*)  d_in[2];
    const int*   edge_rel   = (const int*)  d_in[3];
    const float* time_vec   = (const float*)d_in[4];

    // seed_count may appear as a 1-element int tensor at slot 5, or be absent.
    const int*   seed_ptr = nullptr;
    int bias_base = 5;
    if (n_in >= 9 && in_sizes[5] == 1) {
        seed_ptr  = (const int*)d_in[5];
        bias_base = 6;
    }
    const float* adj_rel_bias  = (const float*)d_in[bias_base + 0];  // [R,H]
    const float* typepair_bias = (const float*)d_in[bias_base + 1];  // [T,T,H]
    const float* temp_bias     = (const float*)d_in[bias_base + 2];  // [B,H]

    float* out = (float*)d_out;
    const int n_edges = in_sizes[1];

    reset_kernel<<<(NN + 255) / 256, 256>>>();
    bucket_kernel<<<(n_edges + 255) / 256, 256>>>(edge_src, edge_dst, edge_rel, n_edges);

    // Fused fill: 4 blocks across j (256 thr * 4 j = 1024 j/blk), one row per blockIdx.y
    dim3 fgrid(NN / JPB, NN);
    fill_kernel<<<fgrid, THR>>>(token_type, time_vec, typepair_bias, temp_bias,
                                adj_rel_bias, seed_ptr, out);
}

// round 14
// speedup vs baseline: 1.0344x; 1.0156x over previous
#include <cuda_runtime.h>
#include <cuda_bf16.h>
#include <math.h>

#define NN   4096
#define TT   8
#define RR   16
#define HH   8
#define BB   21
#define CAP  128   // max edges bucketed per src row (avg 32, Poisson; 128 is ~17 sigma)
#define THR  256   // threads per fill block
#define JPB  (THR * 4)   // j columns covered per block (1024)
#define CPAD 32    // counter padding: 32 ints = 128 B -> one counter per L2 line,
                   // spreads the atomic traffic across LTS slices (hash bits 7-18)

// __device__ scratch (no allocation allowed in kernel_launch)
__device__ int          g_cnt[NN * CPAD];   // counter i lives at g_cnt[i*CPAD]
__device__ unsigned int g_buck[NN * CAP];   // packed (rel<<12)|dst

// ---------------------------------------------------------------------------
__global__ void reset_kernel()
{
    int i = blockIdx.x * blockDim.x + threadIdx.x;
    if (i < NN) g_cnt[i * CPAD] = 0;
}

// Bucket edges by src row. Order within a row is nondeterministic, but the
// fill kernel sums all entries, so the result is order-insensitive (to fp
// rounding, well inside the 1e-3 tolerance).
__global__ void __launch_bounds__(256)
bucket_kernel(const int* __restrict__ edge_src,
              const int* __restrict__ edge_dst,
              const int* __restrict__ edge_rel,
              int n_edges)
{
    int e = blockIdx.x * blockDim.x + threadIdx.x;
    if (e >= n_edges) return;
    const int s = edge_src[e];
    const int d = edge_dst[e];
    const int r = edge_rel[e];
    int pos = atomicAdd(&g_cnt[s * CPAD], 1);
    if (pos < CAP)
        g_buck[s * CAP + pos] = ((unsigned)r << 12) | (unsigned)d;
}

// 8 FADDs, constant smem offsets — inlined into each switch arm.
__device__ __forceinline__ void add_row(float* __restrict__ v,
                                        const float* __restrict__ ab)
{
#pragma unroll
    for (int h = 0; h < HH; h++) v[h] += ab[h];
}

// ---------------------------------------------------------------------------
// Fused fill: out[h,i,j] = typepair[tt[i],tt[j],h] (+ temporal for seed rows)
//                          (+ adj_rel_bias[rel,h] for edges (i -> j))
// blockIdx.y = row i; each thread covers 4 consecutive j, all 8 h planes.
// All accumulation happens in registers; stores are streaming float4.
// ---------------------------------------------------------------------------
__global__ void __launch_bounds__(THR)
fill_kernel(const int*   __restrict__ token_type,
            const float* __restrict__ time_vec,
            const float* __restrict__ typepair_bias,  // [T,T,H] = 512
            const float* __restrict__ temp_bias,      // [B,H]   = 168
            const float* __restrict__ adj_rel_bias,   // [R,H]   = 128
            const int*   __restrict__ seed_ptr,       // may be null
            float*       __restrict__ out)
{
    __shared__ float        s_tp[TT * TT * HH];  // 512
    __shared__ float        s_tb[BB * HH];       // 168
    __shared__ float        s_adj[RR * HH];      // 128
    __shared__ unsigned int s_edges[CAP];
    __shared__ int          s_ecnt;

    const int tid    = threadIdx.x;
    const int i      = blockIdx.y;
    const int blk_j0 = blockIdx.x * JPB;          // this block's j window start

    for (int k = tid; k < TT * TT * HH; k += THR) s_tp[k]  = typepair_bias[k];
    for (int k = tid; k < BB * HH;      k += THR) s_tb[k]  = temp_bias[k];
    for (int k = tid; k < RR * HH;      k += THR) s_adj[k] = adj_rel_bias[k];
    if (tid == 0) s_ecnt = 0;
    __syncthreads();

    // Compacting load: keep only edges whose dst falls in this block's window.
    {
        int c = g_cnt[i * CPAD];
        c = (c < CAP) ? c : CAP;
        if (tid < c) {
            unsigned p = g_buck[i * CAP + tid];
            unsigned d = p & 0xFFFu;
            if (d - (unsigned)blk_j0 < (unsigned)JPB) {
                int pos = atomicAdd(&s_ecnt, 1);
                s_edges[pos] = p;
            }
        }
    }
    __syncthreads();
    const int ecnt = s_ecnt;

    const int j0 = blk_j0 + tid * 4;

    const int tti = token_type[i];                                   // uniform per block
    const int4 ttj = *reinterpret_cast<const int4*>(token_type + j0);

    const int seed = seed_ptr ? *seed_ptr : 128;
    const bool is_seed = (i < seed);

    const float* tp = s_tp + tti * (TT * HH);
    const float* t0 = tp + ttj.x * HH;
    const float* t1 = tp + ttj.y * HH;
    const float* t2 = tp + ttj.z * HH;
    const float* t3 = tp + ttj.w * HH;

    // Register tile: 4 j-lanes x 8 heads (named arrays -> constant indexing)
    float va[HH], vb[HH], vc[HH], vd[HH];
#pragma unroll
    for (int h = 0; h < HH; h++) {
        va[h] = t0[h];
        vb[h] = t1[h];
        vc[h] = t2[h];
        vd[h] = t3[h];
    }

    if (is_seed) {
        const float tvi  = time_vec[i];
        const float4 tvj = *reinterpret_cast<const float4*>(time_vec + j0);
        const float dts[4] = { tvj.x - tvi, tvj.y - tvi, tvj.z - tvi, tvj.w - tvi };
        int bk[4];
#pragma unroll
        for (int q = 0; q < 4; q++) {
            float dt = dts[q];
            float sg = (dt > 0.f) ? 1.f : ((dt < 0.f) ? -1.f : 0.f);
            float sl = sg * log1pf(fabsf(dt) + 1e-6f);
            float nrm = (fminf(fmaxf(sl, -5.f), 5.f) + 5.f) * (1.0f / 10.0f);
            int idx = (int)floorf(nrm * (float)(BB - 1));
            bk[q] = min(max(idx, 0), BB - 1);
        }
        add_row(va, s_tb + bk[0] * HH);
        add_row(vb, s_tb + bk[1] * HH);
        add_row(vc, s_tb + bk[2] * HH);
        add_row(vd, s_tb + bk[3] * HH);
    }

    // Edge scan (block-local, ~8 entries): accumulate adj bias for this thread's j.
    for (int e = 0; e < ecnt; e++) {
        const unsigned p = s_edges[e];            // smem broadcast
        const unsigned d = p & 0xFFFu;
        const unsigned delta = d - (unsigned)j0;  // wraps if d < j0
        if (delta < 4u) {
            const float* ab = s_adj + (p >> 12) * HH;
            switch (delta) {
                case 0u: add_row(va, ab); break;
                case 1u: add_row(vb, ab); break;
                case 2u: add_row(vc, ab); break;
                default: add_row(vd, ab); break;
            }
        }
    }

    const size_t rowbase = (size_t)i * NN + (size_t)j0;
#pragma unroll
    for (int h = 0; h < HH; h++) {
        float4 v = make_float4(va[h], vb[h], vc[h], vd[h]);
        float4* dst = reinterpret_cast<float4*>(out + (size_t)h * NN * NN + rowbase);
        __stcs(dst, v);   // streaming store: output >> L2 capacity
    }
}

// ---------------------------------------------------------------------------
extern "C" void kernel_launch(void* const* d_in, const int* in_sizes, int n_in,
                              void* d_out, int out_size)
{
    const int*   token_type = (const int*)  d_in[0];
    const int*   edge_src   = (const int*)  d_in[1];
    const int*   edge_dst   = (const int*)  d_in[2];
    const int*   edge_rel   = (const int*)  d_in[3];
    const float* time_vec   = (const float*)d_in[4];

    // seed_count may appear as a 1-element int tensor at slot 5, or be absent.
    const int*   seed_ptr = nullptr;
    int bias_base = 5;
    if (n_in >= 9 && in_sizes[5] == 1) {
        seed_ptr  = (const int*)d_in[5];
        bias_base = 6;
    }
    const float* adj_rel_bias  = (const float*)d_in[bias_base + 0];  // [R,H]
    const float* typepair_bias = (const float*)d_in[bias_base + 1];  // [T,T,H]
    const float* temp_bias     = (const float*)d_in[bias_base + 2];  // [B,H]

    float* out = (float*)d_out;
    const int n_edges = in_sizes[1];

    reset_kernel<<<(NN + 255) / 256, 256>>>();
    bucket_kernel<<<(n_edges + 255) / 256, 256>>>(edge_src, edge_dst, edge_rel, n_edges);

    // Fused fill: 4 blocks across j (256 thr * 4 j = 1024 j/blk), one row per blockIdx.y
    dim3 fgrid(NN / JPB, NN);
    fill_kernel<<<fgrid, THR>>>(token_type, time_vec, typepair_bias, temp_bias,
                                adj_rel_bias, seed_ptr, out);
}